// round 2
// baseline (speedup 1.0000x reference)
#include <cuda_runtime.h>
#include <cuda_bf16.h>
#include <stdint.h>

// Problem shape (fixed by the dataset)
#define BB 16
#define SS 16
#define LL 128
#define AA 8
#define TT 8
#define DD 768
#define NC 24              // 3 arg types * 8 args
#define TPB 192            // threads per CTA; each thread owns 4 columns (float4)

// Output layout: concatenation of the returned tuple:
//   mean  [B,S,D]        at 0
//   pred  [B,S,A,D]      at 196608
//   arg0  [B,S,A,D]      at 1769472
//   arg1  [B,S,A,D]      at 3342336
#define OFF_MEAN  0
#define OFF_ARGS  ((size_t)BB * SS * DD)            // 196608
#define PER_TYPE  ((size_t)BB * SS * AA * DD)       // 1572864

__global__ __launch_bounds__(TPB)
void slmuse_fused_kernel(const int* __restrict__ sids_g,
                         const int* __restrict__ mask_g,
                         const int* __restrict__ pred_g,
                         const int* __restrict__ a0_g,
                         const int* __restrict__ a1_g,
                         const float* __restrict__ emb_g,
                         float* __restrict__ out)
{
    const int bs  = blockIdx.x;           // 0..255  (b*S+s)
    const int tid = threadIdx.x;          // 0..191

    __shared__ int           s_sid[LL];
    __shared__ float         s_maskw[LL];
    __shared__ int           s_argids[NC * TT];       // staged arg ids
    __shared__ unsigned char s_w[LL][32];             // dense weights (combo-minor)
    __shared__ int           s_list[NC][LL];          // packed (w<<8)|l
    __shared__ int           s_nnz[NC];
    __shared__ float         s_scale[NC];
    __shared__ float         s_invmask;

    // ---- Phase 0a: stage sentence ids, mask, and arg ids ----
    if (tid < LL) {
        s_sid[tid]   = sids_g[bs * LL + tid];
        s_maskw[tid] = (float)mask_g[bs * LL + tid];
    }
    if (tid < NC * TT) {                  // exactly 192
        int combo = tid >> 3;             // 0..23
        int t     = tid & 7;
        int type  = combo >> 3;           // 0..2
        int a     = combo & 7;
        const int* ap = (type == 0) ? pred_g : (type == 1 ? a0_g : a1_g);
        s_argids[tid] = ap[((size_t)bs * AA + a) * TT + t];
    }
    __syncthreads();

    // ---- Phase 0b: dense weight matrix w[l][combo] ----
    for (int p = tid; p < NC * LL; p += TPB) {
        int combo = p >> 7;               // p / 128
        int l     = p & 127;
        int sid   = s_sid[l];
        int w = 0;
        #pragma unroll
        for (int t = 0; t < TT; t++) {
            int v = s_argids[combo * TT + t];
            w += (v != 0 && v == sid) ? 1 : 0;
        }
        s_w[l][combo] = (unsigned char)w;
    }
    __syncthreads();

    // ---- Phase 0c: compact per-combo lists (threads 0..23),
    //      mask count reduction (threads 160..191) ----
    if (tid < NC) {
        int n = 0, cnt = 0;
        for (int l = 0; l < LL; l++) {
            int w = s_w[l][tid];
            if (w) {
                s_list[tid][n++] = (w << 8) | l;
                cnt += w;
            }
        }
        s_nnz[tid]   = n;
        s_scale[tid] = (cnt > 0) ? (1.0f / (float)cnt) : 0.0f;
    } else if (tid >= 160) {
        int lane = tid - 160;             // 0..31
        float c = s_maskw[lane] + s_maskw[lane + 32] +
                  s_maskw[lane + 64] + s_maskw[lane + 96];
        #pragma unroll
        for (int o = 16; o > 0; o >>= 1)
            c += __shfl_xor_sync(0xffffffffu, c, o);
        if (lane == 0) s_invmask = 1.0f / fmaxf(c, 1.0f);
    }
    __syncthreads();

    // ---- Phase 1: streaming mean pool + sparse arg pools ----
    const int d0 = tid * 4;                                       // 4 columns/thread
    const float4* eb = (const float4*)(emb_g + (size_t)bs * LL * DD + d0);
    const int RS = DD / 4;                                        // row stride = 192 float4

    // mean pool (dense over L) — the one DRAM-streaming pass
    float ax = 0.f, ay = 0.f, az = 0.f, aw = 0.f;
    #pragma unroll 8
    for (int l = 0; l < LL; l++) {
        float4 x = eb[l * RS];
        float  m = s_maskw[l];
        ax = fmaf(m, x.x, ax);
        ay = fmaf(m, x.y, ay);
        az = fmaf(m, x.z, az);
        aw = fmaf(m, x.w, aw);
    }
    {
        float im = s_invmask;
        float4* op = (float4*)(out + OFF_MEAN + (size_t)bs * DD + d0);
        *op = make_float4(ax * im, ay * im, az * im, aw * im);
    }

    // 24 sparse weighted pools (gathers hit L2; the tile was just streamed)
    #pragma unroll 1
    for (int j = 0; j < NC; j++) {
        int n = s_nnz[j];
        float sx = 0.f, sy = 0.f, sz = 0.f, sw = 0.f;
        #pragma unroll 4
        for (int k = 0; k < n; k++) {
            int    e = s_list[j][k];
            float  w = (float)(e >> 8);
            float4 x = eb[(e & 255) * RS];
            sx = fmaf(w, x.x, sx);
            sy = fmaf(w, x.y, sy);
            sz = fmaf(w, x.z, sz);
            sw = fmaf(w, x.w, sw);
        }
        float sc = s_scale[j];
        int type = j >> 3, a = j & 7;
        float4* op = (float4*)(out + OFF_ARGS + (size_t)type * PER_TYPE +
                               ((size_t)(bs * AA + a)) * DD + d0);
        *op = make_float4(sx * sc, sy * sc, sz * sc, sw * sc);
    }
}

extern "C" void kernel_launch(void* const* d_in, const int* in_sizes, int n_in,
                              void* d_out, int out_size)
{
    const int*   sids = (const int*)d_in[0];   // sentence_ids      [B,S,L] int32
    const int*   mask = (const int*)d_in[1];   // attention_masks   [B,S,L] int32
    const int*   pred = (const int*)d_in[2];   // predicate_ids     [B,S,A,T] int32
    const int*   a0   = (const int*)d_in[3];   // arg0_ids          [B,S,A,T] int32
    const int*   a1   = (const int*)d_in[4];   // arg1_ids          [B,S,A,T] int32
    const float* emb  = (const float*)d_in[5]; // sentence_embeddings [B,S,L,D] fp32
    float*       out  = (float*)d_out;

    dim3 grid(BB * SS);   // one CTA per (b,s)
    dim3 block(TPB);
    slmuse_fused_kernel<<<grid, block>>>(sids, mask, pred, a0, a1, emb, out);
}

// round 8
// speedup vs baseline: 1.1355x; 1.1355x over previous
#include <cuda_runtime.h>
#include <cuda_bf16.h>
#include <stdint.h>

// Problem shape (fixed by the dataset)
#define BB 16
#define SS 16
#define LL 128
#define AA 8
#define TT 8
#define DD 768
#define NC 24               // 3 arg types * 8 args
#define TPB 192             // each thread owns one float4 column (192*4 = 768 = D)
#define NCHUNK 8            // L split into 8 chunks of 16 rows
#define CROWS (LL / NCHUNK) // 16 rows per chunk

// Output layout: concatenation of the returned tuple
#define OFF_MEAN  0
#define OFF_ARGS  ((size_t)BB * SS * DD)            // 196608
#define PER_TYPE  ((size_t)BB * SS * AA * DD)       // 1572864

__global__ __launch_bounds__(TPB, 4)
void slmuse_partial_kernel(const int* __restrict__ sids_g,
                           const int* __restrict__ mask_g,
                           const int* __restrict__ pred_g,
                           const int* __restrict__ a0_g,
                           const int* __restrict__ a1_g,
                           const float* __restrict__ emb_g,
                           float* __restrict__ out)
{
    const int bs    = blockIdx.x >> 3;      // 0..255 (b*S+s)
    const int chunk = blockIdx.x & 7;       // 0..7
    const int l0    = chunk * CROWS;
    const int tid   = threadIdx.x;          // 0..191

    __shared__ int           s_sid[LL];
    __shared__ float         s_maskw[LL];
    __shared__ int           s_argids[NC * TT];
    __shared__ unsigned char s_w[LL][32];           // dense weights (combo-minor, padded)
    __shared__ short         s_list[NC][CROWS];     // packed (w<<8)|local_row for this chunk
    __shared__ int           s_nnz[NC];
    __shared__ float         s_scale[NC];           // 1/total_count (0 if count==0)
    __shared__ float         s_invmask;

    // ---- Phase 0a: stage ids and mask ----
    if (tid < LL) {
        s_sid[tid]   = sids_g[bs * LL + tid];
        s_maskw[tid] = (float)mask_g[bs * LL + tid];
    }
    {
        int combo = tid >> 3;               // 0..23
        int t     = tid & 7;
        int type  = combo >> 3;
        int a     = combo & 7;
        const int* ap = (type == 0) ? pred_g : (type == 1 ? a0_g : a1_g);
        s_argids[tid] = ap[((size_t)bs * AA + a) * TT + t];
    }
    __syncthreads();

    // ---- Phase 0b: dense weight matrix w[l][combo] over ALL rows (for counts) ----
    for (int p = tid; p < NC * LL; p += TPB) {
        int combo = p >> 7;
        int l     = p & 127;
        int sid   = s_sid[l];
        int w = 0;
        #pragma unroll
        for (int t = 0; t < TT; t++) {
            int v = s_argids[combo * TT + t];
            w += (v != 0 && v == sid) ? 1 : 0;
        }
        s_w[l][combo] = (unsigned char)w;
    }
    __syncthreads();

    // ---- Phase 0c: global scale + chunk-local compact lists ----
    if (tid < NC) {
        int cnt = 0;
        for (int l = 0; l < LL; l++) cnt += s_w[l][tid];
        s_scale[tid] = (cnt > 0) ? (1.0f / (float)cnt) : 0.0f;
        int n = 0;
        for (int r = 0; r < CROWS; r++) {
            int w = s_w[l0 + r][tid];
            if (w) s_list[tid][n++] = (short)((w << 8) | r);
        }
        s_nnz[tid] = n;
    } else if (tid >= 160) {
        int lane = tid - 160;               // 0..31
        float c = s_maskw[lane] + s_maskw[lane + 32] +
                  s_maskw[lane + 64] + s_maskw[lane + 96];
        #pragma unroll
        for (int o = 16; o > 0; o >>= 1)
            c += __shfl_xor_sync(0xffffffffu, c, o);
        if (lane == 0) s_invmask = 1.0f / fmaxf(c, 1.0f);
    }
    __syncthreads();

    // ---- Phase 1: stream this chunk's 16 rows with a deep load batch ----
    const int d0 = tid * 4;
    const float4* eb = (const float4*)(emb_g + ((size_t)bs * LL + l0) * DD + d0);
    const int RS = DD / 4;                  // 192 float4 row stride

    float4 v[CROWS];
    #pragma unroll
    for (int i = 0; i < CROWS; i++) v[i] = eb[i * RS];   // 16 independent LDG.128

    // mean pool partial (mask-weighted)
    float ax = 0.f, ay = 0.f, az = 0.f, aw = 0.f;
    #pragma unroll
    for (int i = 0; i < CROWS; i++) {
        float m = s_maskw[l0 + i];
        ax = fmaf(m, v[i].x, ax);
        ay = fmaf(m, v[i].y, ay);
        az = fmaf(m, v[i].z, az);
        aw = fmaf(m, v[i].w, aw);
    }
    {
        float im = s_invmask;
        atomicAdd((float4*)(out + OFF_MEAN + (size_t)bs * DD + d0),
                  make_float4(ax * im, ay * im, az * im, aw * im));
    }

    // 24 sparse pools: rows are L1-resident (just streamed); skip empty combos
    #pragma unroll 1
    for (int j = 0; j < NC; j++) {
        int n = s_nnz[j];
        if (n == 0) continue;
        float sx = 0.f, sy = 0.f, sz = 0.f, sw = 0.f;
        for (int k = 0; k < n; k++) {
            int    e = s_list[j][k];
            float  w = (float)(e >> 8);
            float4 x = eb[(e & 255) * RS];
            sx = fmaf(w, x.x, sx);
            sy = fmaf(w, x.y, sy);
            sz = fmaf(w, x.z, sz);
            sw = fmaf(w, x.w, sw);
        }
        float sc = s_scale[j];
        int type = j >> 3, a = j & 7;
        atomicAdd((float4*)(out + OFF_ARGS + (size_t)type * PER_TYPE +
                            ((size_t)(bs * AA + a)) * DD + d0),
                  make_float4(sx * sc, sy * sc, sz * sc, sw * sc));
    }
}

extern "C" void kernel_launch(void* const* d_in, const int* in_sizes, int n_in,
                              void* d_out, int out_size)
{
    const int*   sids = (const int*)d_in[0];   // sentence_ids      [B,S,L] int32
    const int*   mask = (const int*)d_in[1];   // attention_masks   [B,S,L] int32
    const int*   pred = (const int*)d_in[2];   // predicate_ids     [B,S,A,T] int32
    const int*   a0   = (const int*)d_in[3];   // arg0_ids          [B,S,A,T] int32
    const int*   a1   = (const int*)d_in[4];   // arg1_ids          [B,S,A,T] int32
    const float* emb  = (const float*)d_in[5]; // sentence_embeddings [B,S,L,D] fp32
    float*       out  = (float*)d_out;

    cudaMemsetAsync(d_out, 0, (size_t)out_size * sizeof(float));

    dim3 grid(BB * SS * NCHUNK);   // 2048 CTAs: (b*S+s) x L-chunk
    dim3 block(TPB);
    slmuse_partial_kernel<<<grid, block>>>(sids, mask, pred, a0, a1, emb, out);
}

// round 10
// speedup vs baseline: 1.4028x; 1.2353x over previous
#include <cuda_runtime.h>
#include <cuda_bf16.h>
#include <stdint.h>

// Problem shape (fixed by the dataset)
#define BB 16
#define SS 16
#define LL 128
#define AA 8
#define TT 8
#define DD 768
#define NC 24               // 3 arg types * 8 args
#define TPB 192
#define NCHUNK 8            // L split into 8 chunks of 16 rows
#define CROWS (LL / NCHUNK) // 16 rows per chunk
#define NBS (BB * SS)       // 256 (b,s) pairs

// Output layout: concatenation of the returned tuple
#define OFF_MEAN  0
#define OFF_ARGS  ((size_t)BB * SS * DD)            // 196608
#define PER_TYPE  ((size_t)BB * SS * AA * DD)       // 1572864

// Precomputed metadata (device-global scratch; L2-resident, ~1.6 MB)
__device__ float         g_scale[NBS * NC];                    // 1/count (0 if empty)
__device__ float         g_invmask[NBS];                       // 1/max(mask_count,1)
__device__ unsigned char g_nnz[NBS * NCHUNK * NC];             // entries per (bs,chunk,combo)
__device__ short         g_list[NBS * NCHUNK * NC * CROWS];    // packed (w<<8)|local_row

// ---------------------------------------------------------------------------
// Kernel A: per-(b,s) preamble, computed ONCE (grid=256)
// ---------------------------------------------------------------------------
__global__ __launch_bounds__(TPB)
void slmuse_precompute_kernel(const int* __restrict__ sids_g,
                              const int* __restrict__ mask_g,
                              const int* __restrict__ pred_g,
                              const int* __restrict__ a0_g,
                              const int* __restrict__ a1_g)
{
    const int bs  = blockIdx.x;           // 0..255
    const int tid = threadIdx.x;          // 0..191

    __shared__ int           s_sid[LL];
    __shared__ int           s_argids[NC * TT];
    __shared__ unsigned char s_w[LL][32];
    __shared__ int           s_cnt[NCHUNK][NC];

    if (tid < LL) s_sid[tid] = sids_g[bs * LL + tid];
    {
        int combo = tid >> 3;             // 0..23
        int t     = tid & 7;
        int type  = combo >> 3;
        int a     = combo & 7;
        const int* ap = (type == 0) ? pred_g : (type == 1 ? a0_g : a1_g);
        s_argids[tid] = ap[((size_t)bs * AA + a) * TT + t];
    }
    __syncthreads();

    // dense weight matrix w[l][combo]
    for (int p = tid; p < NC * LL; p += TPB) {
        int combo = p >> 7;
        int l     = p & 127;
        int sid   = s_sid[l];
        int w = 0;
        #pragma unroll
        for (int t = 0; t < TT; t++) {
            int v = s_argids[combo * TT + t];
            w += (v != 0 && v == sid) ? 1 : 0;
        }
        s_w[l][combo] = (unsigned char)w;
    }
    __syncthreads();

    // per-(chunk,combo) compaction: 8*24 = 192 threads, one each
    {
        int c = tid / NC;                 // chunk 0..7
        int j = tid % NC;                 // combo 0..23
        int n = 0, cnt = 0;
        short* dst = &g_list[(((size_t)bs * NCHUNK + c) * NC + j) * CROWS];
        #pragma unroll
        for (int r = 0; r < CROWS; r++) {
            int w = s_w[c * CROWS + r][j];
            if (w) { dst[n++] = (short)((w << 8) | r); cnt += w; }
        }
        g_nnz[((size_t)bs * NCHUNK + c) * NC + j] = (unsigned char)n;
        s_cnt[c][j] = cnt;
    }
    __syncthreads();

    if (tid < NC) {
        int total = 0;
        #pragma unroll
        for (int c = 0; c < NCHUNK; c++) total += s_cnt[c][tid];
        g_scale[bs * NC + tid] = (total > 0) ? (1.0f / (float)total) : 0.0f;
    } else if (tid >= 160) {
        int lane = tid - 160;
        float cc = (float)mask_g[bs * LL + lane] +
                   (float)mask_g[bs * LL + lane + 32] +
                   (float)mask_g[bs * LL + lane + 64] +
                   (float)mask_g[bs * LL + lane + 96];
        #pragma unroll
        for (int o = 16; o > 0; o >>= 1)
            cc += __shfl_xor_sync(0xffffffffu, cc, o);
        if (lane == 0) g_invmask[bs] = 1.0f / fmaxf(cc, 1.0f);
    }
}

// ---------------------------------------------------------------------------
// Kernel B: streaming partials (grid=2048), loads issued FIRST
// ---------------------------------------------------------------------------
__global__ __launch_bounds__(TPB, 4)
void slmuse_stream_kernel(const int* __restrict__ mask_g,
                          const float* __restrict__ emb_g,
                          float* __restrict__ out)
{
    const int bs    = blockIdx.x >> 3;    // 0..255
    const int chunk = blockIdx.x & 7;     // 0..7
    const int l0    = chunk * CROWS;
    const int tid   = threadIdx.x;        // 0..191

    // ---- Issue the 16 streaming LDG.128 immediately (before any SMEM work) ----
    const int d0 = tid * 4;
    const float4* eb = (const float4*)(emb_g + ((size_t)bs * LL + l0) * DD + d0);
    const int RS = DD / 4;                // 192 float4 row stride

    float4 v[CROWS];
    #pragma unroll
    for (int i = 0; i < CROWS; i++) v[i] = eb[i * RS];

    // ---- Tiny preamble: load precomputed metadata (overlaps with loads above) ----
    __shared__ float         s_maskw[CROWS];
    __shared__ float         s_scale[NC];
    __shared__ float         s_invmask;
    __shared__ unsigned char s_nnz[NC];
    __shared__ short         s_list[NC * CROWS];   // 384 shorts = 192 ints

    ((int*)s_list)[tid] =
        ((const int*)&g_list[((size_t)bs * NCHUNK + chunk) * NC * CROWS])[tid];
    if (tid < CROWS) s_maskw[tid] = (float)mask_g[bs * LL + l0 + tid];
    else if (tid >= 32 && tid < 32 + NC) s_scale[tid - 32] = g_scale[bs * NC + (tid - 32)];
    else if (tid >= 64 && tid < 64 + NC)
        s_nnz[tid - 64] = g_nnz[((size_t)bs * NCHUNK + chunk) * NC + (tid - 64)];
    else if (tid == 96) s_invmask = g_invmask[bs];
    __syncthreads();

    // ---- mean pool partial ----
    float ax = 0.f, ay = 0.f, az = 0.f, aw = 0.f;
    #pragma unroll
    for (int i = 0; i < CROWS; i++) {
        float m = s_maskw[i];
        ax = fmaf(m, v[i].x, ax);
        ay = fmaf(m, v[i].y, ay);
        az = fmaf(m, v[i].z, az);
        aw = fmaf(m, v[i].w, aw);
    }
    {
        float im = s_invmask;
        atomicAdd((float4*)(out + OFF_MEAN + (size_t)bs * DD + d0),
                  make_float4(ax * im, ay * im, az * im, aw * im));
    }

    // ---- 24 sparse pools (rows are L1-resident; skip empty combos) ----
    #pragma unroll 1
    for (int j = 0; j < NC; j++) {
        int n = s_nnz[j];
        if (n == 0) continue;
        float sx = 0.f, sy = 0.f, sz = 0.f, sw = 0.f;
        const short* lst = &s_list[j * CROWS];
        for (int k = 0; k < n; k++) {
            int    e = lst[k];
            float  w = (float)(e >> 8);
            float4 x = eb[(e & 255) * RS];
            sx = fmaf(w, x.x, sx);
            sy = fmaf(w, x.y, sy);
            sz = fmaf(w, x.z, sz);
            sw = fmaf(w, x.w, sw);
        }
        float sc = s_scale[j];
        int type = j >> 3, a = j & 7;
        atomicAdd((float4*)(out + OFF_ARGS + (size_t)type * PER_TYPE +
                            ((size_t)(bs * AA + a)) * DD + d0),
                  make_float4(sx * sc, sy * sc, sz * sc, sw * sc));
    }
}

extern "C" void kernel_launch(void* const* d_in, const int* in_sizes, int n_in,
                              void* d_out, int out_size)
{
    const int*   sids = (const int*)d_in[0];   // sentence_ids      [B,S,L] int32
    const int*   mask = (const int*)d_in[1];   // attention_masks   [B,S,L] int32
    const int*   pred = (const int*)d_in[2];   // predicate_ids     [B,S,A,T] int32
    const int*   a0   = (const int*)d_in[3];   // arg0_ids          [B,S,A,T] int32
    const int*   a1   = (const int*)d_in[4];   // arg1_ids          [B,S,A,T] int32
    const float* emb  = (const float*)d_in[5]; // sentence_embeddings [B,S,L,D] fp32
    float*       out  = (float*)d_out;

    cudaMemsetAsync(d_out, 0, (size_t)out_size * sizeof(float));
    slmuse_precompute_kernel<<<NBS, TPB>>>(sids, mask, pred, a0, a1);
    slmuse_stream_kernel<<<NBS * NCHUNK, TPB>>>(mask, emb, out);
}

// round 17
// speedup vs baseline: 1.4756x; 1.0519x over previous
#include <cuda_runtime.h>
#include <cuda_bf16.h>
#include <stdint.h>

// Problem shape (fixed by the dataset)
#define BB 16
#define SS 16
#define LL 128
#define AA 8
#define TT 8
#define DD 768
#define NC 24               // 3 arg types * 8 args
#define TPB 192             // one float4 column per thread (192*4 = 768 = D)
#define RPC 8               // rows per pipeline chunk
#define NCH (LL / RPC)      // 16 chunks

// Output layout: concatenation of the returned tuple
#define OFF_MEAN  0
#define OFF_ARGS  ((size_t)BB * SS * DD)            // 196608
#define PER_TYPE  ((size_t)BB * SS * AA * DD)       // 1572864

__global__ __launch_bounds__(TPB, 2)
void slmuse_fused_kernel(const int* __restrict__ sids_g,
                         const int* __restrict__ mask_g,
                         const int* __restrict__ pred_g,
                         const int* __restrict__ a0_g,
                         const int* __restrict__ a1_g,
                         const float* __restrict__ emb_g,
                         float* __restrict__ out)
{
    const int bs  = blockIdx.x;           // 0..255 (b*S+s)
    const int tid = threadIdx.x;          // 0..191

    // ---- Issue the first two row-chunks' loads IMMEDIATELY ----
    const int d0 = tid * 4;
    const float4* eb = (const float4*)(emb_g + (size_t)bs * LL * DD + d0);
    const int RS = DD / 4;                // 192 float4 row stride

    float4 va[RPC], vb[RPC];
    #pragma unroll
    for (int i = 0; i < RPC; i++) va[i] = eb[i * RS];
    #pragma unroll
    for (int i = 0; i < RPC; i++) vb[i] = eb[(RPC + i) * RS];

    // ---- Preamble (once per (b,s)); overlaps the load latency above ----
    __shared__ int           s_sid[LL];
    __shared__ float         s_maskw[LL];
    __shared__ int           s_argids[NC * TT];
    __shared__ unsigned char s_w[LL][32];
    __shared__ short         s_list[NC][LL];   // packed (w<<8)|l
    __shared__ int           s_nnz[NC];
    __shared__ float         s_scale[NC];
    __shared__ float         s_invmask;

    if (tid < LL) {
        s_sid[tid]   = sids_g[bs * LL + tid];
        s_maskw[tid] = (float)mask_g[bs * LL + tid];
    }
    {
        int combo = tid >> 3;             // 0..23
        int t     = tid & 7;
        int type  = combo >> 3;
        int a     = combo & 7;
        const int* ap = (type == 0) ? pred_g : (type == 1 ? a0_g : a1_g);
        s_argids[tid] = ap[((size_t)bs * AA + a) * TT + t];
    }
    __syncthreads();

    for (int p = tid; p < NC * LL; p += TPB) {
        int combo = p >> 7;
        int l     = p & 127;
        int sid   = s_sid[l];
        int w = 0;
        #pragma unroll
        for (int t = 0; t < TT; t++) {
            int v = s_argids[combo * TT + t];
            w += (v != 0 && v == sid) ? 1 : 0;
        }
        s_w[l][combo] = (unsigned char)w;
    }
    __syncthreads();

    if (tid < NC) {
        int n = 0, cnt = 0;
        for (int l = 0; l < LL; l++) {
            int w = s_w[l][tid];
            if (w) { s_list[tid][n++] = (short)((w << 8) | l); cnt += w; }
        }
        s_nnz[tid]   = n;
        s_scale[tid] = (cnt > 0) ? (1.0f / (float)cnt) : 0.0f;
    } else if (tid >= 160) {
        int lane = tid - 160;
        float c = s_maskw[lane] + s_maskw[lane + 32] +
                  s_maskw[lane + 64] + s_maskw[lane + 96];
        #pragma unroll
        for (int o = 16; o > 0; o >>= 1)
            c += __shfl_xor_sync(0xffffffffu, c, o);
        if (lane == 0) s_invmask = 1.0f / fmaxf(c, 1.0f);
    }
    __syncthreads();

    // ---- Streaming mean pool: 16 chunks, double-buffered 8-row batches ----
    float ax = 0.f, ay = 0.f, az = 0.f, aw = 0.f;
    #pragma unroll
    for (int c = 0; c < NCH; c++) {
        float4* buf = (c & 1) ? vb : va;      // static after full unroll
        const int base = c * RPC;
        #pragma unroll
        for (int i = 0; i < RPC; i++) {
            float m = s_maskw[base + i];
            ax = fmaf(m, buf[i].x, ax);
            ay = fmaf(m, buf[i].y, ay);
            az = fmaf(m, buf[i].z, az);
            aw = fmaf(m, buf[i].w, aw);
        }
        if (c + 2 < NCH) {                    // refill this buffer 2 chunks ahead
            const int nb = (c + 2) * RPC;
            #pragma unroll
            for (int i = 0; i < RPC; i++) buf[i] = eb[(nb + i) * RS];
        }
    }
    {
        float im = s_invmask;
        *(float4*)(out + OFF_MEAN + (size_t)bs * DD + d0) =
            make_float4(ax * im, ay * im, az * im, aw * im);
    }

    // ---- 24 sparse pools: gathers hit L1 (tile just streamed); direct stores ----
    #pragma unroll 1
    for (int j = 0; j < NC; j++) {
        int n = s_nnz[j];
        float sx = 0.f, sy = 0.f, sz = 0.f, sw = 0.f;
        const short* lst = s_list[j];
        #pragma unroll 4
        for (int k = 0; k < n; k++) {
            int    e = lst[k];
            float  w = (float)(e >> 8);
            float4 x = eb[(e & 255) * RS];
            sx = fmaf(w, x.x, sx);
            sy = fmaf(w, x.y, sy);
            sz = fmaf(w, x.z, sz);
            sw = fmaf(w, x.w, sw);
        }
        float sc = s_scale[j];                // 0 when n==0 -> zeros, matches ref
        int type = j >> 3, a = j & 7;
        *(float4*)(out + OFF_ARGS + (size_t)type * PER_TYPE +
                   ((size_t)(bs * AA + a)) * DD + d0) =
            make_float4(sx * sc, sy * sc, sz * sc, sw * sc);
    }
}

extern "C" void kernel_launch(void* const* d_in, const int* in_sizes, int n_in,
                              void* d_out, int out_size)
{
    const int*   sids = (const int*)d_in[0];   // sentence_ids      [B,S,L] int32
    const int*   mask = (const int*)d_in[1];   // attention_masks   [B,S,L] int32
    const int*   pred = (const int*)d_in[2];   // predicate_ids     [B,S,A,T] int32
    const int*   a0   = (const int*)d_in[3];   // arg0_ids          [B,S,A,T] int32
    const int*   a1   = (const int*)d_in[4];   // arg1_ids          [B,S,A,T] int32
    const float* emb  = (const float*)d_in[5]; // sentence_embeddings [B,S,L,D] fp32
    float*       out  = (float*)d_out;

    slmuse_fused_kernel<<<BB * SS, TPB>>>(sids, mask, pred, a0, a1, emb, out);
}